// round 4
// baseline (speedup 1.0000x reference)
#include <cuda_runtime.h>
#include <cuda_bf16.h>
#include <math.h>

// LambdaRankLoss: B=32, N=1024, output = scalar mean loss.
//
// loss_b = sum_{i<j} softplus(-sign(y_i-y_j)*(s_i-s_j)) * |g_i-g_j|*|d_i-d_j| / idcg_b
// out    = mean_b(loss_b)
//
// softplus(x) = ln2 * log2(1 + 2^(x*log2e))  -> 2 MUFU ops/pair.
// Pair term symmetric in (i,j): diagonal tiles computed densely, halved.
// 1/idcg and ln2 hoisted to the finalize kernel.
// NOTE: item_mask arrives as 4-byte elements (bool -> int32); read as int*.

#define NMAX 1024
#define BMAX 32
#define TS   128
#define NT   (NMAX / TS)          // 8 tiles
#define NTP  (NT * (NT + 1) / 2)  // 36 tile pairs

__device__ float g_S[BMAX * NMAX];   // scores pre-scaled by log2(e)
__device__ float g_G[BMAX * NMAX];   // gains 2^y - 1
__device__ float g_D[BMAX * NMAX];   // 1/log2(rank+1)
__device__ float g_M[BMAX * NMAX];   // mask as float
__device__ float g_SUM[BMAX];
__device__ float g_IDCG[BMAX];
__device__ int   g_ALLV[BMAX];

__device__ __forceinline__ float ex2f(float x) {
    float r; asm("ex2.approx.ftz.f32 %0, %1;" : "=f"(r) : "f"(x)); return r;
}
__device__ __forceinline__ float lg2af(float x) {
    float r; asm("lg2.approx.ftz.f32 %0, %1;" : "=f"(r) : "f"(x)); return r;
}

__global__ void k_init() {
    int i = threadIdx.x;
    if (i < BMAX) { g_SUM[i] = 0.0f; g_IDCG[i] = 0.0f; g_ALLV[i] = 1; }
}

// grid (B, N/256), block 256: per-item rank / ideal position via stable counting.
__global__ void k_prep(const float* __restrict__ logits,
                       const float* __restrict__ labels,
                       const int* __restrict__ mask, int N) {
    __shared__ float s_sh[NMAX];
    __shared__ float g_sh[NMAX];
    __shared__ float red[8];

    int b = blockIdx.x;
    const float* sc = logits + b * N;
    const float* lb = labels + b * N;

    for (int idx = threadIdx.x; idx < N; idx += blockDim.x) {
        s_sh[idx] = sc[idx];
        g_sh[idx] = exp2f(lb[idx]) - 1.0f;
    }
    __syncthreads();

    int i = blockIdx.y * blockDim.x + threadIdx.x;  // item index, < N
    float si = s_sh[i];
    float gi = g_sh[i];

    int rgt = 0, req = 0, pgt = 0, peq = 0;
#pragma unroll 4
    for (int j = 0; j < NMAX; j++) {
        float sj = s_sh[j];
        float gj = g_sh[j];
        rgt += (sj > si);
        req += (sj == si) && (j < i);
        pgt += (gj > gi);
        peq += (gj == gi) && (j < i);
    }
    int rank = 1 + rgt + req;      // stable descending rank of score
    int pos  = 1 + pgt + peq;      // stable descending position of gain

    float d = 1.0f / log2f((float)(rank + 1));
    float idcg_c = gi / log2f((float)(pos + 1));
    float m = (mask[b * N + i] != 0) ? 1.0f : 0.0f;

    g_S[b * N + i] = si * 1.4426950408889634f;  // prescale by log2(e)
    g_G[b * N + i] = gi;
    g_D[b * N + i] = d;
    g_M[b * N + i] = m;

    // block-reduce idcg partial
    float v = idcg_c;
#pragma unroll
    for (int o = 16; o > 0; o >>= 1) v += __shfl_down_sync(0xffffffffu, v, o);
    int lane = threadIdx.x & 31, wid = threadIdx.x >> 5;
    if (lane == 0) red[wid] = v;

    // all-valid flag for this chunk (also acts as a barrier for red[])
    int av = __syncthreads_and(m != 0.0f);

    if (threadIdx.x == 0) {
        float tot = 0.0f;
#pragma unroll
        for (int w = 0; w < 8; w++) tot += red[w];
        atomicAdd(&g_IDCG[b], tot);
        if (!av) g_ALLV[b] = 0;
    }
}

// grid (36 tile-pairs, B), block 256. Each thread computes an 8x8 pair sub-block.
__global__ void __launch_bounds__(256) k_pairs(int N) {
    __shared__ float si_s[TS], gi_s[TS], di_s[TS], mi_s[TS];
    __shared__ float sj_s[TS], gj_s[TS], dj_s[TS], mj_s[TS];
    __shared__ float red[8];

    int b = blockIdx.y;
    int t = blockIdx.x;
    int ta = 0;
    while (t >= NT - ta) { t -= NT - ta; ta++; }
    int tb = ta + t;   // ta <= tb

    int base = b * N;
    int tid = threadIdx.x;
    if (tid < TS) {
        int gidx = base + ta * TS + tid;
        si_s[tid] = g_S[gidx]; gi_s[tid] = g_G[gidx];
        di_s[tid] = g_D[gidx]; mi_s[tid] = g_M[gidx];
    } else {
        int tj = tid - TS;
        int gidx = base + tb * TS + tj;
        sj_s[tj] = g_S[gidx]; gj_s[tj] = g_G[gidx];
        dj_s[tj] = g_D[gidx]; mj_s[tj] = g_M[gidx];
    }
    __syncthreads();

    int tx = tid & 15, ty = tid >> 4;
    float sr[8], gr[8], dr[8], scc[8], gcc[8], dcc[8];
#pragma unroll
    for (int k = 0; k < 8; k++) {
        int ii = ty * 8 + k;
        sr[k] = si_s[ii]; gr[k] = gi_s[ii]; dr[k] = di_s[ii];
        int jj = tx * 8 + k;
        scc[k] = sj_s[jj]; gcc[k] = gj_s[jj]; dcc[k] = dj_s[jj];
    }

    float acc = 0.0f;
    if (g_ALLV[b]) {
#pragma unroll
        for (int a = 0; a < 8; a++) {
#pragma unroll
            for (int c = 0; c < 8; c++) {
                float ds = sr[a] - scc[c];           // already in log2 units
                float z  = (gr[a] > gcc[c]) ? -ds : ds;
                float t1 = ex2f(z);
                float l  = lg2af(1.0f + t1);
                float w  = fabsf(gr[a] - gcc[c]) * fabsf(dr[a] - dcc[c]);
                acc = fmaf(l, w, acc);
            }
        }
    } else {
        float mr[8], mc[8];
#pragma unroll
        for (int k = 0; k < 8; k++) { mr[k] = mi_s[ty * 8 + k]; mc[k] = mj_s[tx * 8 + k]; }
#pragma unroll
        for (int a = 0; a < 8; a++) {
#pragma unroll
            for (int c = 0; c < 8; c++) {
                float ds = sr[a] - scc[c];
                float z  = (gr[a] > gcc[c]) ? -ds : ds;
                float t1 = ex2f(z);
                float l  = lg2af(1.0f + t1);
                float w  = fabsf(gr[a] - gcc[c]) * fabsf(dr[a] - dcc[c]);
                acc = fmaf(l * w, mr[a] * mc[c], acc);
            }
        }
    }

    // block reduce
#pragma unroll
    for (int o = 16; o > 0; o >>= 1) acc += __shfl_down_sync(0xffffffffu, acc, o);
    if ((tid & 31) == 0) red[tid >> 5] = acc;
    __syncthreads();
    if (tid == 0) {
        float tot = 0.0f;
#pragma unroll
        for (int w = 0; w < 8; w++) tot += red[w];
        if (ta == tb) tot *= 0.5f;   // dense diagonal tile counts each pair twice
        atomicAdd(&g_SUM[b], tot);
    }
}

__global__ void k_final(float* __restrict__ out, int B) {
    int b = threadIdx.x;
    float v = 0.0f;
    if (b < B)
        v = 0.6931471805599453f * g_SUM[b] / fmaxf(g_IDCG[b], 1e-8f);
#pragma unroll
    for (int o = 16; o > 0; o >>= 1) v += __shfl_down_sync(0xffffffffu, v, o);
    if (b == 0) out[0] = v / (float)B;
}

extern "C" void kernel_launch(void* const* d_in, const int* in_sizes, int n_in,
                              void* d_out, int out_size) {
    const float* logits = (const float*)d_in[0];
    const float* labels = (const float*)d_in[1];
    const int* mask = (const int*)d_in[2];

    int N = NMAX;
    int B = in_sizes[0] / N;
    if (B > BMAX) B = BMAX;

    k_init<<<1, 64>>>();
    dim3 gp(B, N / 256);
    k_prep<<<gp, 256>>>(logits, labels, mask, N);
    dim3 g2(NTP, B);
    k_pairs<<<g2, 256>>>(N);
    k_final<<<1, 32>>>((float*)d_out, B);
}

// round 5
// speedup vs baseline: 1.2654x; 1.2654x over previous
#include <cuda_runtime.h>
#include <cuda_bf16.h>
#include <math.h>

// LambdaRankLoss: B=32, N=1024, output = scalar mean loss.
//
// loss_b = sum_{i<j} softplus(-sign(y_i-y_j)*(s_i-s_j)) * |g_i-g_j|*|d_i-d_j| / idcg_b
// out    = mean_b(loss_b)
//
// softplus(x) = ln2 * log2(1 + 2^(x*log2e))  -> 2 MUFU/pair (the roofline).
// Pair term symmetric in (i,j): diagonal tiles dense, halved.
// Sign select fused into one LOP3 using dg's sign bit (dg==0 pairs weigh 0).
// IDCG via 5-bin label histogram (tie-order invariant). 2 kernels total:
// prep (rank/discount/idcg + init) and pairs (with fused last-block finalize).
// item_mask arrives as int32 (bool marshaled 4-byte).

#define NMAX 1024
#define BMAX 32
#define TS   128
#define NT   (NMAX / TS)          // 8
#define NTP  (NT * (NT + 1) / 2)  // 36

__device__ float g_S[BMAX * NMAX];   // scores * log2(e)
__device__ float g_G[BMAX * NMAX];   // gains 2^y - 1
__device__ float g_D[BMAX * NMAX];   // 1/log2(rank+1)
__device__ float g_M[BMAX * NMAX];   // mask as float
__device__ float g_SUM[BMAX];
__device__ float g_IDCG[BMAX];
__device__ int   g_CTR;

__device__ __forceinline__ float ex2f(float x) {
    float r; asm("ex2.approx.ftz.f32 %0, %1;" : "=f"(r) : "f"(x)); return r;
}
__device__ __forceinline__ float lg2af(float x) {
    float r; asm("lg2.approx.ftz.f32 %0, %1;" : "=f"(r) : "f"(x)); return r;
}

// grid (B, 8), block 128. Rank via split stable-comparator count; IDCG via
// label histogram (block y==0 only); init of g_SUM/g_CTR folded in.
__global__ void __launch_bounds__(128) k_prep(const float* __restrict__ logits,
                                              const float* __restrict__ labels,
                                              const int* __restrict__ mask) {
    __shared__ float s_sh[NMAX];
    __shared__ int   hist[5];
    __shared__ float red[4];

    int b   = blockIdx.x;
    int tid = threadIdx.x;
    const float* sc = logits + b * NMAX;
    const float* lb = labels + b * NMAX;

    for (int idx = tid; idx < NMAX; idx += 128) s_sh[idx] = sc[idx];
    if (blockIdx.y == 0 && tid < 5) hist[tid] = 0;
    __syncthreads();

    int i = blockIdx.y * 128 + tid;
    float si = s_sh[i];

    // stable descending rank: 1 + #{j<i: sj>=si} + #{j>=i: sj>si}
    int cnt = 0;
#pragma unroll 8
    for (int j = 0; j < i; j++) cnt += (s_sh[j] >= si);
#pragma unroll 8
    for (int j = i; j < NMAX; j++) cnt += (s_sh[j] > si);
    int rank = cnt + 1;

    float lab = lb[i];
    float gi  = exp2f(lab) - 1.0f;
    float d   = __fdividef(1.0f, __log2f((float)(rank + 1)));

    g_S[b * NMAX + i] = si * 1.4426950408889634f;
    g_G[b * NMAX + i] = gi;
    g_D[b * NMAX + i] = d;
    g_M[b * NMAX + i] = (mask[b * NMAX + i] != 0) ? 1.0f : 0.0f;

    if (blockIdx.y == 0) {
        // 5-bin label histogram over the whole batch
        for (int idx = tid; idx < NMAX; idx += 128) {
            int v = (int)lb[idx];
            v = min(max(v, 0), 4);
            atomicAdd(&hist[v], 1);
        }
        __syncthreads();
        int e4 = hist[4];
        int e3 = e4 + hist[3];
        int e2 = e3 + hist[2];
        int e1 = e2 + hist[1];
        // IDCG = sum over ideal positions p of gain(p)/log2(p+1)
        float part = 0.0f;
        for (int p = tid + 1; p <= NMAX; p += 128) {
            float disc = __fdividef(1.0f, __log2f((float)(p + 1)));
            float g = (p <= e4) ? 15.0f : (p <= e3) ? 7.0f
                    : (p <= e2) ? 3.0f  : (p <= e1) ? 1.0f : 0.0f;
            part += disc * g;
        }
#pragma unroll
        for (int o = 16; o > 0; o >>= 1) part += __shfl_down_sync(0xffffffffu, part, o);
        if ((tid & 31) == 0) red[tid >> 5] = part;
        __syncthreads();
        if (tid == 0) {
            g_IDCG[b] = fmaxf(red[0] + red[1] + red[2] + red[3], 1e-8f);
            g_SUM[b]  = 0.0f;
            if (b == 0) g_CTR = 0;
        }
    }
}

// grid (36, B), block 256; 8x8 pairs per thread; fused final reduction in the
// last block to finish (last-block counter pattern).
__global__ void __launch_bounds__(256) k_pairs(float* __restrict__ out, int B) {
    __shared__ float si_s[TS], gi_s[TS], di_s[TS], mi_s[TS];
    __shared__ float sj_s[TS], gj_s[TS], dj_s[TS], mj_s[TS];
    __shared__ float red[8];
    __shared__ int   s_last;

    int b = blockIdx.y;
    int t = blockIdx.x;
    int ta = 0;
    while (t >= NT - ta) { t -= NT - ta; ta++; }
    int tb = ta + t;   // ta <= tb

    int base = b * NMAX;
    int tid = threadIdx.x;
    float m_local;
    if (tid < TS) {
        int g = base + ta * TS + tid;
        si_s[tid] = g_S[g]; gi_s[tid] = g_G[g];
        di_s[tid] = g_D[g]; m_local = mi_s[tid] = g_M[g];
    } else {
        int tj = tid - TS;
        int g = base + tb * TS + tj;
        sj_s[tj] = g_S[g]; gj_s[tj] = g_G[g];
        dj_s[tj] = g_D[g]; m_local = mj_s[tj] = g_M[g];
    }
    int av = __syncthreads_and(m_local != 0.0f);

    int tx = tid & 15, ty = tid >> 4;
    float sr[8], gr[8], dr[8], scc[8], gcc[8], dcc[8];
#pragma unroll
    for (int k = 0; k < 8; k++) {
        int ii = ty * 8 + k;
        sr[k] = si_s[ii]; gr[k] = gi_s[ii]; dr[k] = di_s[ii];
        int jj = tx * 8 + k;
        scc[k] = sj_s[jj]; gcc[k] = gj_s[jj]; dcc[k] = dj_s[jj];
    }

    float acc0 = 0.0f, acc1 = 0.0f;
    if (av) {
#pragma unroll
        for (int a = 0; a < 8; a++) {
#pragma unroll
            for (int c = 0; c < 8; c++) {
                float ds = sr[a] - scc[c];           // log2 units
                float dg = gr[a] - gcc[c];
                float dd = dr[a] - dcc[c];
                // z = (dg > 0) ? -ds : ds ; dg==0 -> weight 0, don't care.
                // single LOP3: flip sign of ds iff sign bit of dg is 0.
                float z = __uint_as_float(__float_as_uint(ds) ^
                          ((~__float_as_uint(dg)) & 0x80000000u));
                float l = lg2af(1.0f + ex2f(z));
                float w = fabsf(dg) * fabsf(dd);
                if (c & 1) acc1 = fmaf(l, w, acc1);
                else       acc0 = fmaf(l, w, acc0);
            }
        }
    } else {
        float mr[8], mc[8];
#pragma unroll
        for (int k = 0; k < 8; k++) { mr[k] = mi_s[ty * 8 + k]; mc[k] = mj_s[tx * 8 + k]; }
#pragma unroll
        for (int a = 0; a < 8; a++) {
#pragma unroll
            for (int c = 0; c < 8; c++) {
                float ds = sr[a] - scc[c];
                float dg = gr[a] - gcc[c];
                float dd = dr[a] - dcc[c];
                float z = __uint_as_float(__float_as_uint(ds) ^
                          ((~__float_as_uint(dg)) & 0x80000000u));
                float l = lg2af(1.0f + ex2f(z));
                float w = fabsf(dg) * fabsf(dd) * (mr[a] * mc[c]);
                if (c & 1) acc1 = fmaf(l, w, acc1);
                else       acc0 = fmaf(l, w, acc0);
            }
        }
    }

    float acc = acc0 + acc1;
#pragma unroll
    for (int o = 16; o > 0; o >>= 1) acc += __shfl_down_sync(0xffffffffu, acc, o);
    if ((tid & 31) == 0) red[tid >> 5] = acc;
    __syncthreads();
    if (tid == 0) {
        float tot = 0.0f;
#pragma unroll
        for (int w = 0; w < 8; w++) tot += red[w];
        if (ta == tb) tot *= 0.5f;   // dense diagonal counts each pair twice
        atomicAdd(&g_SUM[b], tot);
        __threadfence();
        int total_blocks = gridDim.x * gridDim.y;
        int old = atomicAdd(&g_CTR, 1);
        s_last = (old == total_blocks - 1);
    }
    __syncthreads();

    if (s_last) {
        __threadfence();
        if (tid < 32) {
            float v = 0.0f;
            if (tid < B)
                v = 0.6931471805599453f * atomicAdd(&g_SUM[tid], 0.0f) / g_IDCG[tid];
#pragma unroll
            for (int o = 16; o > 0; o >>= 1) v += __shfl_down_sync(0xffffffffu, v, o);
            if (tid == 0) out[0] = v / (float)B;
        }
    }
}

extern "C" void kernel_launch(void* const* d_in, const int* in_sizes, int n_in,
                              void* d_out, int out_size) {
    const float* logits = (const float*)d_in[0];
    const float* labels = (const float*)d_in[1];
    const int*   mask   = (const int*)d_in[2];

    int B = in_sizes[0] / NMAX;
    if (B > BMAX) B = BMAX;

    dim3 gp(B, NMAX / 128);
    k_prep<<<gp, 128>>>(logits, labels, mask);
    dim3 g2(NTP, B);
    k_pairs<<<g2, 256>>>((float*)d_out, B);
}